// round 3
// baseline (speedup 1.0000x reference)
#include <cuda_runtime.h>
#include <math.h>

#define T_LEN 512
#define BATCH 64
#define ISZ   256
#define HID   512
#define GH    2048   // 4*HID, gate order f,i,o,c
#define NCTA  128

// ---------------- device scratch (no allocations allowed) ----------------
__device__ float g_gx[(size_t)T_LEN * GH * BATCH];  // [t][n=g*512+h][b]
__device__ float g_h[2][HID * BATCH];               // double-buffered h, [h][b]
__device__ unsigned g_bar;                          // grid barrier arrival counter
__device__ volatile unsigned g_epoch;               // grid barrier release epoch

// ---------------- packed f32x2 FMA (sm_100+) ----------------
union F2U { float2 f; unsigned long long u; };
__device__ __forceinline__ float2 ffma2(float2 a, float2 b, float2 c) {
    F2U A, B, C, D; A.f = a; B.f = b; C.f = c;
    asm("fma.rn.f32x2 %0, %1, %2, %3;" : "=l"(D.u) : "l"(A.u), "l"(B.u), "l"(C.u));
    return D.f;
}

// ---------------- init: zero h buffers + barrier state each replay ----------------
__global__ void init_state_kernel() {
    int idx = blockIdx.x * blockDim.x + threadIdx.x;
    if (idx < 2 * HID * BATCH) ((float*)g_h)[idx] = 0.0f;
    if (idx == 0) { g_bar = 0; g_epoch = 0; }
}

// ---------------- gx = x @ Wx^T + bx  -> g_gx[t][n][b] ----------------
__global__ __launch_bounds__(256) void gx_kernel(const float* __restrict__ x,
                                                 const float* __restrict__ Wx,
                                                 const float* __restrict__ bx) {
    extern __shared__ float sm[];
    float* x_s = sm;               // [256][65] padded transpose
    float* Ws  = sm + 256 * 65;    // [32][256]
    const int tid = threadIdx.x;
    const int t   = blockIdx.y;
    const int n0  = blockIdx.x * 32;

    const float* xt = x + (size_t)t * BATCH * ISZ;
    #pragma unroll 4
    for (int r = 0; r < 64; r++) {
        int idx = r * 256 + tid;
        int b = idx >> 8;
        int i = idx & 255;
        x_s[i * 65 + b] = xt[idx];
    }
    const float* Wrow = Wx + (size_t)n0 * ISZ;
    #pragma unroll 4
    for (int r = 0; r < 32; r++) {
        int idx = r * 256 + tid;
        Ws[idx] = Wrow[idx];
    }
    __syncthreads();

    const int b  = tid & 63;
    const int ng = tid >> 6;
    float acc[8];
    #pragma unroll
    for (int j = 0; j < 8; j++) acc[j] = 0.0f;

    const float4* Ws4 = (const float4*)(Ws + (ng * 8) * ISZ);
    #pragma unroll 2
    for (int k4 = 0; k4 < 64; k4++) {
        const int k = k4 * 4;
        const float xa = x_s[(k + 0) * 65 + b];
        const float xb = x_s[(k + 1) * 65 + b];
        const float xc = x_s[(k + 2) * 65 + b];
        const float xd = x_s[(k + 3) * 65 + b];
        #pragma unroll
        for (int j = 0; j < 8; j++) {
            float4 w = Ws4[j * 64 + k4];
            acc[j] += w.x * xa;
            acc[j] += w.y * xb;
            acc[j] += w.z * xc;
            acc[j] += w.w * xd;
        }
    }

    const size_t base = ((size_t)t * GH + n0 + ng * 8) * BATCH + b;
    #pragma unroll
    for (int j = 0; j < 8; j++) {
        g_gx[base + (size_t)j * BATCH] = acc[j] + __ldg(&bx[n0 + ng * 8 + j]);
    }
}

// ---------------- persistent recurrence kernel ----------------
// 128 CTAs (1/SM, all resident) x 512 threads (16 warps). CTA owns h in [h0, h0+4).
// Thread = (hl, ks, bp): hl = h_local (0..3), ks = K quarter (0..3), bp = batch pair.
// Warp = fixed (hl, ks), lanes = bp  ->  W LDS broadcasts, h LDG coalesced.
// Each thread: 4 gate partial dots over K=128 for batches (2bp, 2bp+1) via FFMA2.
// Wh stationary in smem (duplicated pairs). h read via L1-cached LDG (no staging).
__global__ __launch_bounds__(512) void lstm_persistent(
        const float* __restrict__ Wh,
        const float* __restrict__ bh,
        float* __restrict__ h_seq,
        float* __restrict__ out_hlast,
        float* __restrict__ out_clast) {
    extern __shared__ float sm[];
    float2* Wd  = (float2*)sm;            // [16 rows][512 k] dup pairs: 64 KB
    float2* red = (float2*)(sm + 16384);  // [4 g][3 ks][4 hl][32 bp] float2: 12 KB

    const int tid = threadIdx.x;
    const int bp  = tid & 31;
    const int ks  = (tid >> 5) & 3;
    const int hl  = tid >> 7;
    const int h0  = blockIdx.x * 4;
    const int h   = h0 + hl;

    // ---- stage Wh once, duplicated: Wd[row*512+k] = (w, w), row = g*4+hl
    #pragma unroll
    for (int it = 0; it < 16; it++) {
        int idx = it * 512 + tid;          // 0..8191 = row*512 + k
        int r = idx >> 9, k = idx & 511;
        int g = r >> 2, hll = r & 3;
        float w = Wh[((size_t)(g * HID + h0 + hll)) * HID + k];
        Wd[idx] = make_float2(w, w);
    }

    float bhf = 0.f, bhi = 0.f, bho = 0.f, bhc = 0.f;
    if (ks == 0) {
        bhf = __ldg(&bh[0 * HID + h]);
        bhi = __ldg(&bh[1 * HID + h]);
        bho = __ldg(&bh[2 * HID + h]);
        bhc = __ldg(&bh[3 * HID + h]);
    }
    float c0 = 0.0f, c1 = 0.0f;

    const ulonglong2* W0 = (const ulonglong2*)(Wd + (0 * 4 + hl) * 512 + ks * 128);
    const ulonglong2* W1 = (const ulonglong2*)(Wd + (1 * 4 + hl) * 512 + ks * 128);
    const ulonglong2* W2 = (const ulonglong2*)(Wd + (2 * 4 + hl) * 512 + ks * 128);
    const ulonglong2* W3 = (const ulonglong2*)(Wd + (3 * 4 + hl) * 512 + ks * 128);

    __syncthreads();

    int cur = 0;
    for (int t = 0; t < T_LEN; t++) {
        // prefetch gx early (independent of h)
        float2 gx0, gx1, gx2, gx3;
        if (ks == 0) {
            const float* gp = g_gx + ((size_t)t * GH + h) * BATCH + 2 * bp;
            gx0 = __ldg((const float2*)(gp + (size_t)0 * HID * BATCH));
            gx1 = __ldg((const float2*)(gp + (size_t)1 * HID * BATCH));
            gx2 = __ldg((const float2*)(gp + (size_t)2 * HID * BATCH));
            gx3 = __ldg((const float2*)(gp + (size_t)3 * HID * BATCH));
        }

        // ---- 4 gate partial dot products over this thread's K quarter
        const float2* hp = (const float2*)(g_h[cur]) + ks * 128 * 32 + bp; // k-local kl -> hp[kl*32]
        float2 a0 = make_float2(0.f, 0.f), a1 = a0, a2 = a0, a3 = a0;

        #pragma unroll 4
        for (int it2 = 0; it2 < 32; it2++) {
            const float2 hv0 = __ldg(hp + (4 * it2 + 0) * 32);
            const float2 hv1 = __ldg(hp + (4 * it2 + 1) * 32);
            const float2 hv2 = __ldg(hp + (4 * it2 + 2) * 32);
            const float2 hv3 = __ldg(hp + (4 * it2 + 3) * 32);
            ulonglong2 w; F2U wa, wb;
            w = W0[2 * it2];     wa.u = w.x; wb.u = w.y;
            a0 = ffma2(hv0, wa.f, a0); a0 = ffma2(hv1, wb.f, a0);
            w = W0[2 * it2 + 1]; wa.u = w.x; wb.u = w.y;
            a0 = ffma2(hv2, wa.f, a0); a0 = ffma2(hv3, wb.f, a0);
            w = W1[2 * it2];     wa.u = w.x; wb.u = w.y;
            a1 = ffma2(hv0, wa.f, a1); a1 = ffma2(hv1, wb.f, a1);
            w = W1[2 * it2 + 1]; wa.u = w.x; wb.u = w.y;
            a1 = ffma2(hv2, wa.f, a1); a1 = ffma2(hv3, wb.f, a1);
            w = W2[2 * it2];     wa.u = w.x; wb.u = w.y;
            a2 = ffma2(hv0, wa.f, a2); a2 = ffma2(hv1, wb.f, a2);
            w = W2[2 * it2 + 1]; wa.u = w.x; wb.u = w.y;
            a2 = ffma2(hv2, wa.f, a2); a2 = ffma2(hv3, wb.f, a2);
            w = W3[2 * it2];     wa.u = w.x; wb.u = w.y;
            a3 = ffma2(hv0, wa.f, a3); a3 = ffma2(hv1, wb.f, a3);
            w = W3[2 * it2 + 1]; wa.u = w.x; wb.u = w.y;
            a3 = ffma2(hv2, wa.f, a3); a3 = ffma2(hv3, wb.f, a3);
        }

        // ---- reduce the 4 K-quarters: ks>0 write partials, ks==0 combines
        if (ks != 0) {
            float2* rp = red + ((size_t)(ks - 1) * 4 + hl) * 32 + bp;  // [g][ks-1][hl][bp]
            rp[0]    = a0;
            rp[384]  = a1;
            rp[768]  = a2;
            rp[1152] = a3;
        }
        __syncthreads();

        if (ks == 0) {
            const float2* rp = red + hl * 32 + bp;
            float2 r;
            r = rp[0];        a0.x += r.x; a0.y += r.y;
            r = rp[128];      a0.x += r.x; a0.y += r.y;
            r = rp[256];      a0.x += r.x; a0.y += r.y;
            r = rp[384];      a1.x += r.x; a1.y += r.y;
            r = rp[384+128];  a1.x += r.x; a1.y += r.y;
            r = rp[384+256];  a1.x += r.x; a1.y += r.y;
            r = rp[768];      a2.x += r.x; a2.y += r.y;
            r = rp[768+128];  a2.x += r.x; a2.y += r.y;
            r = rp[768+256];  a2.x += r.x; a2.y += r.y;
            r = rp[1152];     a3.x += r.x; a3.y += r.y;
            r = rp[1152+128]; a3.x += r.x; a3.y += r.y;
            r = rp[1152+256]; a3.x += r.x; a3.y += r.y;

            const float pf0 = a0.x + gx0.x + bhf, pf1 = a0.y + gx0.y + bhf;
            const float pi0 = a1.x + gx1.x + bhi, pi1 = a1.y + gx1.y + bhi;
            const float po0 = a2.x + gx2.x + bho, po1 = a2.y + gx2.y + bho;
            const float pc0 = a3.x + gx3.x + bhc, pc1 = a3.y + gx3.y + bhc;

            const float f0 = 1.0f / (1.0f + __expf(-pf0));
            const float f1 = 1.0f / (1.0f + __expf(-pf1));
            const float i0 = 1.0f / (1.0f + __expf(-pi0));
            const float i1 = 1.0f / (1.0f + __expf(-pi1));
            const float o0 = 1.0f / (1.0f + __expf(-po0));
            const float o1 = 1.0f / (1.0f + __expf(-po1));
            const float q0 = tanhf(pc0);
            const float q1 = tanhf(pc1);

            c0 = f0 * c0 + i0 * q0;
            c1 = f1 * c1 + i1 * q1;
            const float hn0 = o0 * tanhf(c0);
            const float hn1 = o1 * tanhf(c1);

            *(float2*)(g_h[cur ^ 1] + h * BATCH + 2 * bp) = make_float2(hn0, hn1);

            float* so = h_seq + ((size_t)t * BATCH + 2 * bp) * HID + h;
            so[0]   = hn0;
            so[HID] = hn1;
            if (t == T_LEN - 1) {
                out_hlast[(size_t)(2 * bp) * HID + h]     = hn0;
                out_hlast[(size_t)(2 * bp + 1) * HID + h] = hn1;
                out_clast[(size_t)(2 * bp) * HID + h]     = c0;
                out_clast[(size_t)(2 * bp + 1) * HID + h] = c1;
            }
        }

        // ---- grid barrier: atomic arrival, spin on read-mostly epoch flag
        __syncthreads();
        if (tid == 0) {
            __threadfence();
            unsigned old = atomicAdd(&g_bar, 1u);
            if (old == (unsigned)(t + 1) * NCTA - 1) {
                g_epoch = (unsigned)(t + 1);        // release
            } else {
                while (g_epoch <= (unsigned)t) { }  // acquire spin
            }
            __threadfence();
        }
        __syncthreads();
        cur ^= 1;
    }
}

// ---------------- launch ----------------
extern "C" void kernel_launch(void* const* d_in, const int* in_sizes, int n_in,
                              void* d_out, int out_size) {
    const float* x  = (const float*)d_in[0];
    const float* Wx = (const float*)d_in[1];
    const float* bx = (const float*)d_in[2];
    const float* Wh = (const float*)d_in[3];
    const float* bh = (const float*)d_in[4];

    float* out       = (float*)d_out;
    float* out_hlast = out + (size_t)T_LEN * BATCH * HID;
    float* out_clast = out_hlast + (size_t)BATCH * HID;

    const int gx_smem = (256 * 65 + 32 * 256) * sizeof(float);   // 99328 B
    const int ps_smem = (16384 + 3072) * sizeof(float);          // 77824 B
    cudaFuncSetAttribute(gx_kernel,       cudaFuncAttributeMaxDynamicSharedMemorySize, gx_smem);
    cudaFuncSetAttribute(lstm_persistent, cudaFuncAttributeMaxDynamicSharedMemorySize, ps_smem);

    init_state_kernel<<<128, 512>>>();
    gx_kernel<<<dim3(64, 512), 256, gx_smem>>>(x, Wx, bx);
    lstm_persistent<<<NCTA, 512, ps_smem>>>(Wh, bh, out, out_hlast, out_clast);
}

// round 4
// speedup vs baseline: 1.0788x; 1.0788x over previous
#include <cuda_runtime.h>
#include <math.h>
#include <stdint.h>

#define T_LEN 512
#define BATCH 64
#define ISZ   256
#define HID   512
#define GH    2048   // 4*HID, gate order f,i,o,c
#define NCTA  128
#define WROW  516    // padded row stride (float2 units) for Wd

// ---------------- device scratch (no allocations allowed) ----------------
__device__ float g_gx[(size_t)T_LEN * GH * BATCH];  // [t][n=g*512+h][b]
__device__ float g_h[2][HID * BATCH];               // double-buffered h, [h][b]
__device__ volatile unsigned g_flags[NCTA];         // per-CTA step counters

// ---------------- packed f32x2 FMA (sm_100+) ----------------
union F2U { float2 f; unsigned long long u; };
__device__ __forceinline__ float2 ffma2(float2 a, float2 b, float2 c) {
    F2U A, B, C, D; A.f = a; B.f = b; C.f = c;
    asm("fma.rn.f32x2 %0, %1, %2, %3;" : "=l"(D.u) : "l"(A.u), "l"(B.u), "l"(C.u));
    return D.f;
}

__device__ __forceinline__ float fast_sigmoid(float x) {
    return __fdividef(1.0f, 1.0f + __expf(-x));
}
__device__ __forceinline__ float fast_tanh(float x) {
    return __fdividef(2.0f, 1.0f + __expf(-2.0f * x)) - 1.0f;
}

// ---------------- init: zero h buffers + flags each replay ----------------
__global__ void init_state_kernel() {
    int idx = blockIdx.x * blockDim.x + threadIdx.x;
    if (idx < 2 * HID * BATCH) ((float*)g_h)[idx] = 0.0f;
    if (idx < NCTA) g_flags[idx] = 0u;
}

// ---------------- gx = x @ Wx^T + bx  -> g_gx[t][n][b] ----------------
__global__ __launch_bounds__(256) void gx_kernel(const float* __restrict__ x,
                                                 const float* __restrict__ Wx,
                                                 const float* __restrict__ bx) {
    extern __shared__ float sm[];
    float* x_s = sm;               // [256][65] padded transpose
    float* Ws  = sm + 256 * 65;    // [32][256]
    const int tid = threadIdx.x;
    const int t   = blockIdx.y;
    const int n0  = blockIdx.x * 32;

    const float* xt = x + (size_t)t * BATCH * ISZ;
    #pragma unroll 4
    for (int r = 0; r < 64; r++) {
        int idx = r * 256 + tid;
        int b = idx >> 8;
        int i = idx & 255;
        x_s[i * 65 + b] = xt[idx];
    }
    const float* Wrow = Wx + (size_t)n0 * ISZ;
    #pragma unroll 4
    for (int r = 0; r < 32; r++) {
        int idx = r * 256 + tid;
        Ws[idx] = Wrow[idx];
    }
    __syncthreads();

    const int b  = tid & 63;
    const int ng = tid >> 6;
    float acc[8];
    #pragma unroll
    for (int j = 0; j < 8; j++) acc[j] = 0.0f;

    const float4* Ws4 = (const float4*)(Ws + (ng * 8) * ISZ);
    #pragma unroll 2
    for (int k4 = 0; k4 < 64; k4++) {
        const int k = k4 * 4;
        const float xa = x_s[(k + 0) * 65 + b];
        const float xb = x_s[(k + 1) * 65 + b];
        const float xc = x_s[(k + 2) * 65 + b];
        const float xd = x_s[(k + 3) * 65 + b];
        #pragma unroll
        for (int j = 0; j < 8; j++) {
            float4 w = Ws4[j * 64 + k4];
            acc[j] += w.x * xa;
            acc[j] += w.y * xb;
            acc[j] += w.z * xc;
            acc[j] += w.w * xd;
        }
    }

    const size_t base = ((size_t)t * GH + n0 + ng * 8) * BATCH + b;
    #pragma unroll
    for (int j = 0; j < 8; j++) {
        g_gx[base + (size_t)j * BATCH] = acc[j] + __ldg(&bx[n0 + ng * 8 + j]);
    }
}

// ---------------- persistent recurrence kernel ----------------
// 128 CTAs (1/SM, all resident) x 256 threads. CTA owns h in [h0, h0+4).
// Warp = (ks, hlp, bq); lane = (hl2, bpl):
//   ks  = K half (0..1), hl = hlp*2+hl2 (0..3), bp = bq*16+bpl (0..31).
// h LDS.64: 16 distinct float2 (dup over hl2) = 128B = 1 wavefront.
// W LDS.128 broadcast (2 addresses, padded rows -> no bank clash) = 1 wavefront.
// Wh stationary in smem (dup pairs); h staged per step via cp.async.cg (L2 path).
__global__ __launch_bounds__(256) void lstm_persistent(
        const float* __restrict__ Wh,
        const float* __restrict__ bh,
        float* __restrict__ h_seq,
        float* __restrict__ out_hlast,
        float* __restrict__ out_clast) {
    extern __shared__ float sm[];
    float2* Wd  = (float2*)sm;                       // [16 rows][WROW] dup pairs
    float*  hs  = sm + 2 * 16 * WROW;                // [512 k][64 b] floats (128 KB)
    float2* red = (float2*)(hs + HID * BATCH);       // [4 g][4 hl][32 bp] float2 (4 KB)

    const int tid  = threadIdx.x;
    const int lane = tid & 31;
    const int warp = tid >> 5;
    const int bpl  = lane & 15;
    const int hl2  = lane >> 4;
    const int bq   = warp & 1;
    const int hlp  = (warp >> 1) & 1;
    const int ks   = warp >> 2;
    const int hl   = hlp * 2 + hl2;
    const int bp   = bq * 16 + bpl;
    const int bid  = blockIdx.x;
    const int h0   = bid * 4;
    const int h    = h0 + hl;

    // ---- stage Wh once, duplicated: Wd[r*WROW+k] = (w, w), r = g*4+hl
    #pragma unroll
    for (int it = 0; it < 32; it++) {
        int idx = it * 256 + tid;              // 0..8191 = r*512 + k
        int r = idx >> 9, k = idx & 511;
        int g = r >> 2, hll = r & 3;
        float w = Wh[((size_t)(g * HID + h0 + hll)) * HID + k];
        Wd[r * WROW + k] = make_float2(w, w);
    }

    const bool epi = (ks == 0);
    float bhf = 0.f, bhi = 0.f, bho = 0.f, bhc = 0.f;
    if (epi) {
        bhf = __ldg(&bh[0 * HID + h]);
        bhi = __ldg(&bh[1 * HID + h]);
        bho = __ldg(&bh[2 * HID + h]);
        bhc = __ldg(&bh[3 * HID + h]);
    }
    float c0 = 0.0f, c1 = 0.0f;

    const ulonglong2* W0 = (const ulonglong2*)(Wd + (0 * 4 + hl) * WROW + ks * 256);
    const ulonglong2* W1 = (const ulonglong2*)(Wd + (1 * 4 + hl) * WROW + ks * 256);
    const ulonglong2* W2 = (const ulonglong2*)(Wd + (2 * 4 + hl) * WROW + ks * 256);
    const ulonglong2* W3 = (const ulonglong2*)(Wd + (3 * 4 + hl) * WROW + ks * 256);

    __syncthreads();

    int cur = 0;
    for (int t = 0; t < T_LEN; t++) {
        // ---- gx prefetch: independent of h, issue before the flag wait
        float2 gx0, gx1, gx2, gx3;
        if (epi) {
            const float* gp = g_gx + ((size_t)t * GH + h) * BATCH + 2 * bp;
            gx0 = __ldg((const float2*)(gp + (size_t)0 * HID * BATCH));
            gx1 = __ldg((const float2*)(gp + (size_t)1 * HID * BATCH));
            gx2 = __ldg((const float2*)(gp + (size_t)2 * HID * BATCH));
            gx3 = __ldg((const float2*)(gp + (size_t)3 * HID * BATCH));
        }

        // ---- wait: all CTAs have produced h for step t (flags[i] >= t)
        if (t > 0) {
            if (tid < NCTA) {
                while (g_flags[tid] < (unsigned)t) { __nanosleep(32); }
            }
            __syncthreads();
        }

        // ---- stage h: global (L2, st.cg-written) -> smem via cp.async.cg
        {
            const float4* src = (const float4*)g_h[cur];
            uint32_t dbase = (uint32_t)__cvta_generic_to_shared(hs);
            #pragma unroll 8
            for (int it = 0; it < 32; it++) {
                int idx = it * 256 + tid;
                uint32_t d = dbase + idx * 16;
                asm volatile("cp.async.cg.shared.global [%0], [%1], 16;"
                             :: "r"(d), "l"(src + idx));
            }
            asm volatile("cp.async.commit_group;");
            asm volatile("cp.async.wait_group 0;");
        }
        __syncthreads();

        // ---- 4 gate partial dots over this thread's K half (batch pair packed)
        const float2* hp = (const float2*)hs + ks * 256 * 32 + bp;
        float2 a0 = make_float2(0.f, 0.f), a1 = a0, a2 = a0, a3 = a0;

        #pragma unroll 8
        for (int kk = 0; kk < 64; kk++) {
            const float2 hv0 = hp[(4 * kk + 0) * 32];
            const float2 hv1 = hp[(4 * kk + 1) * 32];
            const float2 hv2 = hp[(4 * kk + 2) * 32];
            const float2 hv3 = hp[(4 * kk + 3) * 32];
            ulonglong2 w; F2U wa, wb;
            w = W0[2 * kk];     wa.u = w.x; wb.u = w.y;
            a0 = ffma2(hv0, wa.f, a0); a0 = ffma2(hv1, wb.f, a0);
            w = W0[2 * kk + 1]; wa.u = w.x; wb.u = w.y;
            a0 = ffma2(hv2, wa.f, a0); a0 = ffma2(hv3, wb.f, a0);
            w = W1[2 * kk];     wa.u = w.x; wb.u = w.y;
            a1 = ffma2(hv0, wa.f, a1); a1 = ffma2(hv1, wb.f, a1);
            w = W1[2 * kk + 1]; wa.u = w.x; wb.u = w.y;
            a1 = ffma2(hv2, wa.f, a1); a1 = ffma2(hv3, wb.f, a1);
            w = W2[2 * kk];     wa.u = w.x; wb.u = w.y;
            a2 = ffma2(hv0, wa.f, a2); a2 = ffma2(hv1, wb.f, a2);
            w = W2[2 * kk + 1]; wa.u = w.x; wb.u = w.y;
            a2 = ffma2(hv2, wa.f, a2); a2 = ffma2(hv3, wb.f, a2);
            w = W3[2 * kk];     wa.u = w.x; wb.u = w.y;
            a3 = ffma2(hv0, wa.f, a3); a3 = ffma2(hv1, wb.f, a3);
            w = W3[2 * kk + 1]; wa.u = w.x; wb.u = w.y;
            a3 = ffma2(hv2, wa.f, a3); a3 = ffma2(hv3, wb.f, a3);
        }

        // ---- reduce the two K halves (conflict-free layout [g][hl][bp])
        if (!epi) {
            float2* rp = red + hl * 32 + bp;
            rp[0]   = a0;
            rp[128] = a1;
            rp[256] = a2;
            rp[384] = a3;
        }
        __syncthreads();

        if (epi) {
            const float2* rp = red + hl * 32 + bp;
            float2 r;
            r = rp[0];   a0.x += r.x; a0.y += r.y;
            r = rp[128]; a1.x += r.x; a1.y += r.y;
            r = rp[256]; a2.x += r.x; a2.y += r.y;
            r = rp[384]; a3.x += r.x; a3.y += r.y;

            const float pf0 = a0.x + gx0.x + bhf, pf1 = a0.y + gx0.y + bhf;
            const float pi0 = a1.x + gx1.x + bhi, pi1 = a1.y + gx1.y + bhi;
            const float po0 = a2.x + gx2.x + bho, po1 = a2.y + gx2.y + bho;
            const float pc0 = a3.x + gx3.x + bhc, pc1 = a3.y + gx3.y + bhc;

            const float f0 = fast_sigmoid(pf0), f1 = fast_sigmoid(pf1);
            const float i0 = fast_sigmoid(pi0), i1 = fast_sigmoid(pi1);
            const float o0 = fast_sigmoid(po0), o1 = fast_sigmoid(po1);
            const float q0 = fast_tanh(pc0),    q1 = fast_tanh(pc1);

            c0 = f0 * c0 + i0 * q0;
            c1 = f1 * c1 + i1 * q1;
            const float hn0 = o0 * fast_tanh(c0);
            const float hn1 = o1 * fast_tanh(c1);

            // next-step h (L2-resident: st.cg so consumers' cp.async.cg see it)
            __stcg((float2*)(g_h[cur ^ 1] + h * BATCH + 2 * bp),
                   make_float2(hn0, hn1));

            float* so = h_seq + ((size_t)t * BATCH + 2 * bp) * HID + h;
            so[0]   = hn0;
            so[HID] = hn1;
            if (t == T_LEN - 1) {
                out_hlast[(size_t)(2 * bp) * HID + h]     = hn0;
                out_hlast[(size_t)(2 * bp + 1) * HID + h] = hn1;
                out_clast[(size_t)(2 * bp) * HID + h]     = c0;
                out_clast[(size_t)(2 * bp + 1) * HID + h] = c1;
            }
            __threadfence();   // make h stores visible before the flag release
        }

        // ---- release: this CTA finished step t
        __syncthreads();
        if (tid == 0) g_flags[bid] = (unsigned)(t + 1);
        cur ^= 1;
    }
}

// ---------------- launch ----------------
extern "C" void kernel_launch(void* const* d_in, const int* in_sizes, int n_in,
                              void* d_out, int out_size) {
    const float* x  = (const float*)d_in[0];
    const float* Wx = (const float*)d_in[1];
    const float* bx = (const float*)d_in[2];
    const float* Wh = (const float*)d_in[3];
    const float* bh = (const float*)d_in[4];

    float* out       = (float*)d_out;
    float* out_hlast = out + (size_t)T_LEN * BATCH * HID;
    float* out_clast = out_hlast + (size_t)BATCH * HID;

    const int gx_smem = (256 * 65 + 32 * 256) * sizeof(float);            // 99328 B
    const int ps_smem = (2 * 16 * WROW + HID * BATCH + 1024) * sizeof(float); // 201216 B
    cudaFuncSetAttribute(gx_kernel,       cudaFuncAttributeMaxDynamicSharedMemorySize, gx_smem);
    cudaFuncSetAttribute(lstm_persistent, cudaFuncAttributeMaxDynamicSharedMemorySize, ps_smem);

    init_state_kernel<<<128, 512>>>();
    gx_kernel<<<dim3(64, 512), 256, gx_smem>>>(x, Wx, bx);
    lstm_persistent<<<NCTA, 256, ps_smem>>>(Wh, bh, out, out_hlast, out_clast);
}